// round 12
// baseline (speedup 1.0000x reference)
#include <cuda_runtime.h>
#include <cuda_fp16.h>
#include <math.h>
#include <stdint.h>

#define Bn 4
#define Cn 192
#define Hn 128
#define Wn 128
#define Ln (Hn * Wn)          // 16384
#define HEADS 8
#define CH 24
#define HID 510
#define TIMED 256

// ---------------- scratch ----------------
__device__ float g_mod[2 * Bn * 2 * Cn];
__device__ float g_y  [(size_t)Bn * Ln * Cn];
__device__ float g_x1 [(size_t)Bn * Ln * Cn];
__device__ float g_xt [(size_t)Bn * Ln * Cn];
__device__ __align__(16) uint32_t g_bufA[(size_t)Bn * Ln * 512];  // fp16x2 GEMM outs
__device__ __align__(16) uint32_t g_bufB[(size_t)Bn * Ln * 288];  // fp16x2 qkv dwconv out
__device__ float g_S  [Bn * HEADS * CH * CH];
__device__ float g_rn [Bn * 2 * Cn];
__device__ __align__(16) uint32_t g_wh[249856];                   // fp16 weight pairs
__device__ __align__(16) uint32_t g_ah[(size_t)Bn * Ln * 256];    // fp16 activation pairs

// ---------------- helpers ----------------
__device__ __forceinline__ uint32_t packh(float x, float y) {
    __half2 h = __floats2half2_rn(x, y);
    return *(uint32_t*)&h;
}
__device__ __forceinline__ float2 unph(uint32_t u) {
    return __half22float2(*(__half2*)&u);
}
#define MMA16816(d, a, b0v, b1v) \
    asm volatile("mma.sync.aligned.m16n8k16.row.col.f32.f16.f16.f32 " \
        "{%0,%1,%2,%3}, {%4,%5,%6,%7}, {%8,%9}, {%0,%1,%2,%3};" \
        : "+f"((d)[0]), "+f"((d)[1]), "+f"((d)[2]), "+f"((d)[3]) \
        : "r"((a)[0]), "r"((a)[1]), "r"((a)[2]), "r"((a)[3]), "r"(b0v), "r"(b1v))

// ---------------- fused weight prep: all four weights in one launch ----------------
__global__ void prep_all(const float* __restrict__ qkv, const float* __restrict__ proj,
                         const float* __restrict__ c1, const float* __restrict__ c2,
                         uint32_t* __restrict__ oh) {
    int seg = blockIdx.y;
    const float* W; int O, K, KP2, dst, total;
    if (seg == 0)      { W = qkv;  O = 576;  K = 192; KP2 = 96;  dst = 0;      total = 576 * 96; }
    else if (seg == 1) { W = proj; O = 192;  K = 192; KP2 = 96;  dst = 55296;  total = 192 * 96; }
    else if (seg == 2) { W = c1;   O = 1020; K = 192; KP2 = 96;  dst = 73728;  total = 1152 * 96; }
    else               { W = c2;   O = 192;  K = 510; KP2 = 256; dst = 184320; total = 192 * 256; }
    for (int idx = blockIdx.x * 256 + threadIdx.x; idx < total; idx += gridDim.x * 256) {
        int o = idx / KP2, j = idx - o * KP2;
        int k0 = 2 * j;
        float f0 = (o < O && k0     < K) ? W[(size_t)o * K + k0]     : 0.f;
        float f1 = (o < O && k0 + 1 < K) ? W[(size_t)o * K + k0 + 1] : 0.f;
        oh[dst + idx] = packh(f0, f1);
    }
}

// ---------------- fp16 HMMA GEMM, double-buffered smem ----------------
// MODE 0: fp32 out [l,o] (+resid);  MODE 1: fp16-pair out stride YSH.
#define AST 12
template<int MODE>
__global__ __launch_bounds__(256)
void mma_hmma(const uint32_t* __restrict__ Ah, int SA,
              const uint32_t* __restrict__ Wh, int SW,
              const float* __restrict__ bias, const float* __restrict__ resid,
              float* __restrict__ Yf, uint32_t* __restrict__ Yh, int YSH,
              int YS, int Oreal, int KC) {
    __shared__ uint32_t sA[2][128 * AST], sW[2][192 * AST];

    int tid = threadIdx.x, w = tid >> 5, lane = tid & 31;
    int gid = lane >> 2, tig = lane & 3;
    int l0 = blockIdx.x * 128, o0 = blockIdx.y * 192, b = blockIdx.z;
    int wm = (w >> 1) * 32, wn = (w & 1) * 96;

    int arow = tid >> 1, au = tid & 1;
    size_t agoff = ((size_t)b * Ln + l0 + arow) * SA + au * 4;
    int asoff = arow * AST + au * 4;
    int wrow0 = tid >> 1, wu = tid & 1;
    size_t wgoff0 = (size_t)(o0 + wrow0) * SW + wu * 4;
    int wsoff0 = wrow0 * AST + wu * 4;
    int wrow1 = (tid + 256) >> 1;
    size_t wgoff1 = (size_t)(o0 + wrow1) * SW + wu * 4;
    int wsoff1 = wrow1 * AST + wu * 4;
    bool w1ok = tid < 128;

    float acc[2][12][4];
    #pragma unroll
    for (int i = 0; i < 2; i++)
        #pragma unroll
        for (int j = 0; j < 12; j++)
            #pragma unroll
            for (int q = 0; q < 4; q++) acc[i][j][q] = 0.f;

    *(uint4*)(sA[0] + asoff)  = *(const uint4*)(Ah + agoff);
    *(uint4*)(sW[0] + wsoff0) = *(const uint4*)(Wh + wgoff0);
    if (w1ok) *(uint4*)(sW[0] + wsoff1) = *(const uint4*)(Wh + wgoff1);
    __syncthreads();

    for (int c = 0; c < KC; c++) {
        bool nxt = (c + 1 < KC);
        uint4 pa, pw0, pw1;
        if (nxt) {
            size_t d = (size_t)(c + 1) * 8;
            pa  = *(const uint4*)(Ah + agoff + d);
            pw0 = *(const uint4*)(Wh + wgoff0 + d);
            if (w1ok) pw1 = *(const uint4*)(Wh + wgoff1 + d);
        }
        int cb = c & 1;
        uint32_t a[2][4];
        #pragma unroll
        for (int i = 0; i < 2; i++) {
            int base = (wm + i * 16 + gid) * AST + tig;
            a[i][0] = sA[cb][base];      a[i][1] = sA[cb][base + 8 * AST];
            a[i][2] = sA[cb][base + 4];  a[i][3] = sA[cb][base + 8 * AST + 4];
        }
        #pragma unroll
        for (int j = 0; j < 12; j++) {
            int nb = (wn + j * 8 + gid) * AST + tig;
            uint32_t b0 = sW[cb][nb], b1 = sW[cb][nb + 4];
            MMA16816(acc[0][j], a[0], b0, b1);
            MMA16816(acc[1][j], a[1], b0, b1);
        }
        if (nxt) {
            int nb2 = cb ^ 1;
            *(uint4*)(sA[nb2] + asoff)  = pa;
            *(uint4*)(sW[nb2] + wsoff0) = pw0;
            if (w1ok) *(uint4*)(sW[nb2] + wsoff1) = pw1;
            __syncthreads();
        }
    }

    if (MODE == 1) {
        #pragma unroll
        for (int j = 0; j < 12; j++) {
            int o = o0 + wn + j * 8 + tig * 2;
            if (o >= Oreal) continue;
            float b0 = bias[o], b1 = bias[o + 1];
            int ou = o >> 1;
            #pragma unroll
            for (int i = 0; i < 2; i++) {
                int r = l0 + wm + i * 16 + gid;
                Yh[((size_t)b * Ln + r)     * YSH + ou] = packh(acc[i][j][0] + b0, acc[i][j][1] + b1);
                Yh[((size_t)b * Ln + r + 8) * YSH + ou] = packh(acc[i][j][2] + b0, acc[i][j][3] + b1);
            }
        }
    } else {
        #pragma unroll
        for (int j = 0; j < 12; j++) {
            int o = o0 + wn + j * 8 + tig * 2;
            if (o >= Oreal) continue;
            float b0 = bias[o], b1 = bias[o + 1];
            #pragma unroll
            for (int i = 0; i < 2; i++) {
                int r = l0 + wm + i * 16 + gid;
                size_t y0 = ((size_t)b * Ln + r) * YS + o;
                size_t y1 = ((size_t)b * Ln + r + 8) * YS + o;
                float2 v0 = make_float2(acc[i][j][0] + b0, acc[i][j][1] + b1);
                float2 v1 = make_float2(acc[i][j][2] + b0, acc[i][j][3] + b1);
                if (resid) {
                    float2 q0 = *(const float2*)(resid + y0);
                    float2 q1 = *(const float2*)(resid + y1);
                    v0.x += q0.x; v0.y += q0.y; v1.x += q1.x; v1.y += q1.y;
                }
                *(float2*)(Yf + y0) = v0;
                *(float2*)(Yf + y1) = v1;
            }
        }
    }
}

// ---------------- transpose in: x[C,L] -> xt[L,C] ----------------
__global__ void t_in(const float* __restrict__ x, float* __restrict__ xt) {
    __shared__ float t[32][33];
    int b = blockIdx.z, l0 = blockIdx.x * 32, c0 = blockIdx.y * 32;
    int tx = threadIdx.x, ty = threadIdx.y;
    #pragma unroll
    for (int k = 0; k < 4; k++)
        t[ty + 8 * k][tx] = x[((size_t)b * Cn + c0 + ty + 8 * k) * Ln + l0 + tx];
    __syncthreads();
    #pragma unroll
    for (int k = 0; k < 4; k++)
        xt[((size_t)b * Ln + l0 + ty + 8 * k) * Cn + c0 + tx] = t[tx][ty + 8 * k];
}

// ---------------- transpose out + residual ----------------
__global__ void t_out(const float* __restrict__ a, const float* __restrict__ y,
                      float* __restrict__ out) {
    __shared__ float t[32][33];
    int b = blockIdx.z, l0 = blockIdx.x * 32, c0 = blockIdx.y * 32;
    int tx = threadIdx.x, ty = threadIdx.y;
    #pragma unroll
    for (int k = 0; k < 4; k++) {
        size_t idx = ((size_t)b * Ln + l0 + ty + 8 * k) * Cn + c0 + tx;
        t[ty + 8 * k][tx] = a[idx] + y[idx];
    }
    __syncthreads();
    #pragma unroll
    for (int k = 0; k < 4; k++)
        out[((size_t)b * Cn + c0 + ty + 8 * k) * Ln + l0 + tx] = t[tx][ty + 8 * k];
}

// ---------------- time MLP: warp-per-output ----------------
__global__ void time_mlp_kernel(const float* __restrict__ t_emb,
                                const float* __restrict__ aw, const float* __restrict__ ab,
                                const float* __restrict__ fw, const float* __restrict__ fb) {
    int bb = blockIdx.x;               // 0..7 : (branch, b)
    int branch = bb >> 2, b = bb & 3;
    const float* w   = branch ? fw : aw;
    const float* bia = branch ? fb : ab;
    __shared__ float ts[TIMED];
    int tid = threadIdx.x, warp = tid >> 5, lane = tid & 31;
    if (tid < TIMED) {
        float t = t_emb[b * TIMED + tid];
        ts[tid] = t / (1.f + expf(-t));
    }
    __syncthreads();
    int o = blockIdx.y * 8 + warp;     // grid.y = 48 -> 384 outputs
    const float* wr = w + (size_t)o * TIMED;
    float s = 0.f;
    #pragma unroll
    for (int i = 0; i < 8; i++) s += ts[lane + 32 * i] * wr[lane + 32 * i];
    #pragma unroll
    for (int off = 16; off; off >>= 1) s += __shfl_xor_sync(0xffffffffu, s, off);
    if (lane == 0)
        g_mod[((size_t)branch * Bn + b) * (2 * Cn) + o] = s + bia[o];
}

// ---------------- LN + modulation -> fp16 pair plane ----------------
__global__ void ln_mod_cl(const float* __restrict__ x, const float* __restrict__ w,
                          const float* __restrict__ bb, int branch,
                          uint32_t* __restrict__ uh) {
    int warp = threadIdx.x >> 5, lane = threadIdx.x & 31;
    int b = blockIdx.y;
    size_t l = (size_t)blockIdx.x * 8 + warp;
    const float* xr = x + ((size_t)b * Ln + l) * Cn;
    float2 v[3];
    float s = 0.f, q = 0.f;
    #pragma unroll
    for (int j = 0; j < 3; j++) {
        v[j] = *(const float2*)(xr + 2 * lane + 64 * j);
        s += v[j].x + v[j].y;
        q += v[j].x * v[j].x + v[j].y * v[j].y;
    }
    #pragma unroll
    for (int off = 16; off; off >>= 1) {
        s += __shfl_xor_sync(0xffffffffu, s, off);
        q += __shfl_xor_sync(0xffffffffu, q, off);
    }
    float mean = s * (1.f / Cn);
    float var  = fmaxf((q - s * mean) * (1.f / (Cn - 1)), 0.f);
    float inv  = 1.f / (sqrtf(var) + 1e-6f);
    const float* md = g_mod + ((size_t)branch * Bn + b) * (2 * Cn);
    size_t ub = ((size_t)b * Ln + l) * 96;
    #pragma unroll
    for (int j = 0; j < 3; j++) {
        int c = 2 * lane + 64 * j;
        float t0 = ((v[j].x - mean) * inv * w[c]     + bb[c])     * (1.f + md[c])     + md[Cn + c];
        float t1 = ((v[j].y - mean) * inv * w[c + 1] + bb[c + 1]) * (1.f + md[c + 1]) + md[Cn + c + 1];
        uh[ub + lane + 32 * j] = packh(t0, t1);
    }
}

// ---------------- qkv depthwise 3x3 (fp16 in/out, fused q/k sum-squares) --------
__global__ void dwconv_cl(const uint32_t* __restrict__ in, const float* __restrict__ w,
                          const float* __restrict__ bias, uint32_t* __restrict__ outp) {
    int c2 = threadIdx.x;
    if (c2 >= 144) return;
    int l = blockIdx.x, b = blockIdx.z;
    int h = l >> 7, wx = l & 127;
    const uint32_t* base = in + (size_t)b * Ln * 288 + 2 * c2;
    float wr[9][4];
    #pragma unroll
    for (int i = 0; i < 4; i++)
        #pragma unroll
        for (int t = 0; t < 9; t++)
            wr[t][i] = __ldg(&w[(c2 * 4 + i) * 9 + t]);
    float a0 = 0.f, a1 = 0.f, a2 = 0.f, a3 = 0.f;
    #pragma unroll
    for (int kh = 0; kh < 3; kh++) {
        int h2 = h + kh - 1;
        if (h2 < 0 || h2 >= Hn) continue;
        #pragma unroll
        for (int kw = 0; kw < 3; kw++) {
            int w2 = wx + kw - 1;
            if (w2 < 0 || w2 >= Wn) continue;
            uint2 uu = *(const uint2*)(base + (size_t)(h2 * Wn + w2) * 288);
            float2 f0 = unph(uu.x), f1 = unph(uu.y);
            int t = kh * 3 + kw;
            a0 += wr[t][0] * f0.x; a1 += wr[t][1] * f0.y;
            a2 += wr[t][2] * f1.x; a3 += wr[t][3] * f1.y;
        }
    }
    a0 += bias[c2 * 4]; a1 += bias[c2 * 4 + 1]; a2 += bias[c2 * 4 + 2]; a3 += bias[c2 * 4 + 3];
    size_t ob = ((size_t)b * Ln + l) * 288 + 2 * c2;
    outp[ob]     = packh(a0, a1);
    outp[ob + 1] = packh(a2, a3);
    if (c2 < 96) {
        float* rn = g_rn + b * (2 * Cn) + 4 * c2;
        atomicAdd(rn,     a0 * a0);
        atomicAdd(rn + 1, a1 * a1);
        atomicAdd(rn + 2, a2 * a2);
        atomicAdd(rn + 3, a3 * a3);
    }
}

// ---------------- GDFN dwconv + gate (fp16 in/out) ----------------
__global__ void dwgate_cl(const uint32_t* __restrict__ in, const float* __restrict__ w,
                          const float* __restrict__ bias, uint32_t* __restrict__ uh) {
    int j = threadIdx.x;
    int l = blockIdx.x, b = blockIdx.z;
    size_t ub = ((size_t)b * Ln + l) * 256;
    if (j == 255) { uh[ub + 255] = 0u; return; }
    int c0 = 2 * j;
    int h = l >> 7, wx = l & 127;
    const uint32_t* base = in + (size_t)b * Ln * 510;
    float w1[9][2], w2[9][2];
    #pragma unroll
    for (int i = 0; i < 2; i++)
        #pragma unroll
        for (int t = 0; t < 9; t++) {
            w1[t][i] = __ldg(&w[(c0 + i) * 9 + t]);
            w2[t][i] = __ldg(&w[(510 + c0 + i) * 9 + t]);
        }
    float2 a1 = make_float2(0.f, 0.f), a2 = make_float2(0.f, 0.f);
    #pragma unroll
    for (int kh = 0; kh < 3; kh++) {
        int h2 = h + kh - 1;
        if (h2 < 0 || h2 >= Hn) continue;
        #pragma unroll
        for (int kw = 0; kw < 3; kw++) {
            int w2i = wx + kw - 1;
            if (w2i < 0 || w2i >= Wn) continue;
            const uint32_t* prow = base + (size_t)(h2 * Wn + w2i) * 510;
            float2 v1 = unph(prow[j]), v2 = unph(prow[255 + j]);
            int t = kh * 3 + kw;
            a1.x += w1[t][0] * v1.x; a1.y += w1[t][1] * v1.y;
            a2.x += w2[t][0] * v2.x; a2.y += w2[t][1] * v2.y;
        }
    }
    float o0 = (a1.x + bias[c0])     * (a2.x + bias[510 + c0]);
    float o1 = (a1.y + bias[c0 + 1]) * (a2.y + bias[510 + c0 + 1]);
    uh[ub + j] = packh(o0, o1);
}

// ---------------- attention logits (fp16 input) ----------------
__global__ void attn_logits_cl(const uint32_t* __restrict__ qk) {
    int bh = blockIdx.y;  int b = bh >> 3, h = bh & 7;
    int l0 = blockIdx.x * 128;
    __shared__ float qs[CH * 129], ks[CH * 129];
    const uint32_t* qbase = qk + ((size_t)b * Ln + l0) * 288 + h * 12;
    const uint32_t* kbase = qbase + 96;
    for (int i = threadIdx.x; i < 12 * 128; i += 256) {
        int l = i / 12, u = i - l * 12;
        float2 fq = unph(qbase[(size_t)l * 288 + u]);
        float2 fk = unph(kbase[(size_t)l * 288 + u]);
        qs[(2 * u) * 129 + l]     = fq.x;
        qs[(2 * u + 1) * 129 + l] = fq.y;
        ks[(2 * u) * 129 + l]     = fk.x;
        ks[(2 * u + 1) * 129 + l] = fk.y;
    }
    __syncthreads();
    int t = threadIdx.x;
    if (t < 144) {
        int c0 = (t / 12) * 2, d0 = (t % 12) * 2;
        float a00 = 0, a01 = 0, a10 = 0, a11 = 0;
        #pragma unroll 4
        for (int l = 0; l < 128; l++) {
            float q0 = qs[c0 * 129 + l], q1 = qs[(c0 + 1) * 129 + l];
            float k0 = ks[d0 * 129 + l], k1 = ks[(d0 + 1) * 129 + l];
            a00 += q0 * k0; a01 += q0 * k1; a10 += q1 * k0; a11 += q1 * k1;
        }
        float* S = g_S + (size_t)bh * (CH * CH);
        atomicAdd(&S[ c0      * CH + d0    ], a00);
        atomicAdd(&S[ c0      * CH + d0 + 1], a01);
        atomicAdd(&S[(c0 + 1) * CH + d0    ], a10);
        atomicAdd(&S[(c0 + 1) * CH + d0 + 1], a11);
    }
}

// ---------------- softmax ----------------
__global__ void attn_softmax_kernel(const float* __restrict__ temp) {
    int bh = blockIdx.x;  int b = bh >> 3, h = bh & 7;
    int c = threadIdx.x;
    if (c >= CH) return;
    float* S = g_S + (size_t)bh * (CH * CH) + c * CH;
    float rq = 1.f / fmaxf(sqrtf(g_rn[b * (2 * Cn) + h * CH + c]), 1e-12f);
    float tp = temp[h];
    float lo[CH];
    float mx = -1e30f;
    #pragma unroll
    for (int d = 0; d < CH; d++) {
        float rk = 1.f / fmaxf(sqrtf(g_rn[b * (2 * Cn) + Cn + h * CH + d]), 1e-12f);
        float v = S[d] * rq * rk * tp;
        lo[d] = v; mx = fmaxf(mx, v);
    }
    float sum = 0.f;
    #pragma unroll
    for (int d = 0; d < CH; d++) { lo[d] = expf(lo[d] - mx); sum += lo[d]; }
    float inv = 1.f / sum;
    #pragma unroll
    for (int d = 0; d < CH; d++) S[d] = lo[d] * inv;
}

// ---------------- attention apply (fp16 v) -> fp16 pair plane ----------------
__global__ void attn_apply_cl(const uint32_t* __restrict__ qkv, uint32_t* __restrict__ uh) {
    int b = blockIdx.z, h = blockIdx.y;
    int l = blockIdx.x * 128 + threadIdx.x;
    __shared__ float P[CH * CH];
    for (int i = threadIdx.x; i < CH * CH; i += 128)
        P[i] = g_S[(size_t)(b * HEADS + h) * (CH * CH) + i];
    __syncthreads();
    const uint32_t* vr = qkv + ((size_t)b * Ln + l) * 288 + 192 + h * 12;
    float vv[CH];
    #pragma unroll
    for (int d = 0; d < 12; d++) {
        float2 f = unph(vr[d]);
        vv[2 * d] = f.x; vv[2 * d + 1] = f.y;
    }
    float acc[CH];
    #pragma unroll
    for (int c = 0; c < CH; c++) {
        float a = 0.f;
        #pragma unroll
        for (int d = 0; d < CH; d++) a += P[c * CH + d] * vv[d];
        acc[c] = a;
    }
    size_t ub = ((size_t)b * Ln + l) * 96 + h * 12;
    #pragma unroll
    for (int i = 0; i < 12; i++)
        uh[ub + i] = packh(acc[2 * i], acc[2 * i + 1]);
}

// ---------------- launch ----------------
extern "C" void kernel_launch(void* const* d_in, const int* in_sizes, int n_in,
                              void* d_out, int out_size) {
    const float* x       = (const float*)d_in[0];
    const float* t_emb   = (const float*)d_in[1];
    const float* n1_w    = (const float*)d_in[2];
    const float* n1_b    = (const float*)d_in[3];
    const float* temp    = (const float*)d_in[4];
    const float* a_qkv_w = (const float*)d_in[5];
    const float* a_qkv_b = (const float*)d_in[6];
    const float* a_dw_w  = (const float*)d_in[7];
    const float* a_dw_b  = (const float*)d_in[8];
    const float* a_proj_w= (const float*)d_in[9];
    const float* a_proj_b= (const float*)d_in[10];
    const float* a_t_w   = (const float*)d_in[11];
    const float* a_t_b   = (const float*)d_in[12];
    const float* n2_w    = (const float*)d_in[13];
    const float* n2_b    = (const float*)d_in[14];
    const float* f_c1_w  = (const float*)d_in[15];
    const float* f_c1_b  = (const float*)d_in[16];
    const float* f_dw_w  = (const float*)d_in[17];
    const float* f_dw_b  = (const float*)d_in[18];
    const float* f_c2_w  = (const float*)d_in[19];
    const float* f_c2_b  = (const float*)d_in[20];
    const float* f_t_w   = (const float*)d_in[21];
    const float* f_t_b   = (const float*)d_in[22];
    float* out = (float*)d_out;

    float *p_y, *p_x1, *p_xt, *p_S, *p_rn;
    uint32_t *p_wh, *p_ah, *p_bufA, *p_bufB;
    cudaGetSymbolAddress((void**)&p_y,    g_y);
    cudaGetSymbolAddress((void**)&p_x1,   g_x1);
    cudaGetSymbolAddress((void**)&p_xt,   g_xt);
    cudaGetSymbolAddress((void**)&p_bufA, g_bufA);
    cudaGetSymbolAddress((void**)&p_bufB, g_bufB);
    cudaGetSymbolAddress((void**)&p_S,    g_S);
    cudaGetSymbolAddress((void**)&p_rn,   g_rn);
    cudaGetSymbolAddress((void**)&p_wh,   g_wh);
    cudaGetSymbolAddress((void**)&p_ah,   g_ah);

    prep_all<<<dim3(108, 4), 256>>>(a_qkv_w, a_proj_w, f_c1_w, f_c2_w, p_wh);

    cudaMemsetAsync(p_S,  0, sizeof(float) * Bn * HEADS * CH * CH);
    cudaMemsetAsync(p_rn, 0, sizeof(float) * Bn * 2 * Cn);

    time_mlp_kernel<<<dim3(8, 48), 256>>>(t_emb, a_t_w, a_t_b, f_t_w, f_t_b);
    t_in<<<dim3(Ln / 32, Cn / 32, Bn), dim3(32, 8)>>>(x, p_xt);

    // ================= Block 1: MDTA =================
    ln_mod_cl<<<dim3(Ln / 8, Bn), 256>>>(p_xt, n1_w, n1_b, 0, p_ah);
    mma_hmma<1><<<dim3(Ln / 128, 3, Bn), 256>>>(p_ah, 96, p_wh, 96,
                                                a_qkv_b, nullptr, nullptr, p_bufA, 288, 0, 576, 12);
    dwconv_cl<<<dim3(Ln, 1, Bn), 160>>>(p_bufA, a_dw_w, a_dw_b, p_bufB);
    attn_logits_cl<<<dim3(Ln / 128, Bn * HEADS), 256>>>(p_bufB);
    attn_softmax_kernel<<<Bn * HEADS, 32>>>(temp);
    attn_apply_cl<<<dim3(Ln / 128, HEADS, Bn), 128>>>(p_bufB, p_ah);
    mma_hmma<0><<<dim3(Ln / 128, 1, Bn), 256>>>(p_ah, 96, p_wh + 55296, 96,
                                                a_proj_b, p_xt, p_x1, nullptr, 0, 192, 192, 12);

    // ================= Block 2: GDFN =================
    ln_mod_cl<<<dim3(Ln / 8, Bn), 256>>>(p_x1, n2_w, n2_b, 1, p_ah);
    mma_hmma<1><<<dim3(Ln / 128, 6, Bn), 256>>>(p_ah, 96, p_wh + 73728, 96,
                                                f_c1_b, nullptr, nullptr, p_bufA, 510, 0, 1020, 12);
    dwgate_cl<<<dim3(Ln, 1, Bn), 256>>>(p_bufA, f_dw_w, f_dw_b, p_ah);
    mma_hmma<0><<<dim3(Ln / 128, 1, Bn), 256>>>(p_ah, 256, p_wh + 184320, 256,
                                                f_c2_b, nullptr, p_y, nullptr, 0, 192, 192, 32);
    t_out<<<dim3(Ln / 32, Cn / 32, Bn), dim3(32, 8)>>>(p_x1, p_y, out);
}

// round 14
// speedup vs baseline: 3.1498x; 3.1498x over previous
#include <cuda_runtime.h>
#include <cuda_fp16.h>
#include <math.h>
#include <stdint.h>

#define Bn 4
#define Cn 192
#define Hn 128
#define Wn 128
#define Ln (Hn * Wn)          // 16384
#define HEADS 8
#define CH 24
#define HID 510
#define TIMED 256

// ---------------- scratch ----------------
__device__ float g_mod[2 * Bn * 2 * Cn];
__device__ float g_y  [(size_t)Bn * Ln * Cn];
__device__ float g_x1 [(size_t)Bn * Ln * Cn];
__device__ float g_xt [(size_t)Bn * Ln * Cn];
__device__ __align__(16) uint32_t g_bufA[(size_t)Bn * Ln * 512];  // fp16x2 GEMM outs
__device__ __align__(16) uint32_t g_bufB[(size_t)Bn * Ln * 288];  // fp16x2 qkv dwconv out
__device__ float g_S  [Bn * HEADS * CH * CH];
__device__ float g_rn [Bn * 2 * Cn];
__device__ __align__(16) uint32_t g_wh[249856];                   // fp16 weight pairs
__device__ __align__(16) uint32_t g_ah[(size_t)Bn * Ln * 256];    // fp16 activation pairs

// ---------------- helpers ----------------
__device__ __forceinline__ uint32_t packh(float x, float y) {
    __half2 h = __floats2half2_rn(x, y);
    return *(uint32_t*)&h;
}
__device__ __forceinline__ float2 unph(uint32_t u) {
    return __half22float2(*(__half2*)&u);
}
#define MMA16816(d, a, b0v, b1v) \
    asm volatile("mma.sync.aligned.m16n8k16.row.col.f32.f16.f16.f32 " \
        "{%0,%1,%2,%3}, {%4,%5,%6,%7}, {%8,%9}, {%0,%1,%2,%3};" \
        : "+f"((d)[0]), "+f"((d)[1]), "+f"((d)[2]), "+f"((d)[3]) \
        : "r"((a)[0]), "r"((a)[1]), "r"((a)[2]), "r"((a)[3]), "r"(b0v), "r"(b1v))

// ---------------- fused weight prep: all four weights in one launch ----------------
__global__ void prep_all(const float* __restrict__ qkv, const float* __restrict__ proj,
                         const float* __restrict__ c1, const float* __restrict__ c2,
                         uint32_t* __restrict__ oh) {
    int seg = blockIdx.y;
    const float* W; int O, K, KP2, dst, total;
    if (seg == 0)      { W = qkv;  O = 576;  K = 192; KP2 = 96;  dst = 0;      total = 576 * 96; }
    else if (seg == 1) { W = proj; O = 192;  K = 192; KP2 = 96;  dst = 55296;  total = 192 * 96; }
    else if (seg == 2) { W = c1;   O = 1020; K = 192; KP2 = 96;  dst = 73728;  total = 1152 * 96; }
    else               { W = c2;   O = 192;  K = 510; KP2 = 256; dst = 184320; total = 192 * 256; }
    for (int idx = blockIdx.x * 256 + threadIdx.x; idx < total; idx += gridDim.x * 256) {
        int o = idx / KP2, j = idx - o * KP2;
        int k0 = 2 * j;
        float f0 = (o < O && k0     < K) ? W[(size_t)o * K + k0]     : 0.f;
        float f1 = (o < O && k0 + 1 < K) ? W[(size_t)o * K + k0 + 1] : 0.f;
        oh[dst + idx] = packh(f0, f1);
    }
}

// ---------------- fp16 single-pass HMMA GEMM, double-buffered smem ----------------
#define AST 12
__global__ __launch_bounds__(256)
void mma_hmma(const uint32_t* __restrict__ Ah, int SA,
              const uint32_t* __restrict__ Wh, int SW,
              const float* __restrict__ bias, const float* __restrict__ resid,
              float* __restrict__ Yf, uint32_t* __restrict__ Yh, int YSH,
              int YS, int Oreal, int KC) {
    __shared__ uint32_t sA[2][128 * AST], sW[2][192 * AST];

    int tid = threadIdx.x, w = tid >> 5, lane = tid & 31;
    int gid = lane >> 2, tig = lane & 3;
    int l0 = blockIdx.x * 128, o0 = blockIdx.y * 192, b = blockIdx.z;
    int wm = (w >> 1) * 32, wn = (w & 1) * 96;

    int arow = tid >> 1, au = tid & 1;
    size_t agoff = ((size_t)b * Ln + l0 + arow) * SA + au * 4;
    int asoff = arow * AST + au * 4;
    int wrow0 = tid >> 1, wu = tid & 1;
    size_t wgoff0 = (size_t)(o0 + wrow0) * SW + wu * 4;
    int wsoff0 = wrow0 * AST + wu * 4;
    int wrow1 = (tid + 256) >> 1;
    size_t wgoff1 = (size_t)(o0 + wrow1) * SW + wu * 4;
    int wsoff1 = wrow1 * AST + wu * 4;
    bool w1ok = tid < 128;

    float acc[2][12][4];
    #pragma unroll
    for (int i = 0; i < 2; i++)
        #pragma unroll
        for (int j = 0; j < 12; j++)
            #pragma unroll
            for (int q = 0; q < 4; q++) acc[i][j][q] = 0.f;

    *(uint4*)(sA[0] + asoff)  = *(const uint4*)(Ah + agoff);
    *(uint4*)(sW[0] + wsoff0) = *(const uint4*)(Wh + wgoff0);
    if (w1ok) *(uint4*)(sW[0] + wsoff1) = *(const uint4*)(Wh + wgoff1);
    __syncthreads();

    for (int c = 0; c < KC; c++) {
        bool nxt = (c + 1 < KC);
        uint4 pa, pw0, pw1;
        if (nxt) {
            size_t d = (size_t)(c + 1) * 8;
            pa  = *(const uint4*)(Ah + agoff + d);
            pw0 = *(const uint4*)(Wh + wgoff0 + d);
            if (w1ok) pw1 = *(const uint4*)(Wh + wgoff1 + d);
        }
        int cb = c & 1;
        uint32_t a[2][4];
        #pragma unroll
        for (int i = 0; i < 2; i++) {
            int base = (wm + i * 16 + gid) * AST + tig;
            a[i][0] = sA[cb][base];      a[i][1] = sA[cb][base + 8 * AST];
            a[i][2] = sA[cb][base + 4];  a[i][3] = sA[cb][base + 8 * AST + 4];
        }
        #pragma unroll
        for (int j = 0; j < 12; j++) {
            int nb = (wn + j * 8 + gid) * AST + tig;
            uint32_t b0 = sW[cb][nb], b1 = sW[cb][nb + 4];
            MMA16816(acc[0][j], a[0], b0, b1);
            MMA16816(acc[1][j], a[1], b0, b1);
        }
        if (nxt) {
            int nb2 = cb ^ 1;
            *(uint4*)(sA[nb2] + asoff)  = pa;
            *(uint4*)(sW[nb2] + wsoff0) = pw0;
            if (w1ok) *(uint4*)(sW[nb2] + wsoff1) = pw1;
            __syncthreads();
        }
    }

    // ---- epilogue ----
    if (Yh) {
        #pragma unroll
        for (int j = 0; j < 12; j++) {
            int o = o0 + wn + j * 8 + tig * 2;
            if (o >= Oreal) continue;
            float b0 = bias[o], b1 = bias[o + 1];
            int ou = o >> 1;
            #pragma unroll
            for (int i = 0; i < 2; i++) {
                int r = l0 + wm + i * 16 + gid;
                Yh[((size_t)b * Ln + r)     * YSH + ou] = packh(acc[i][j][0] + b0, acc[i][j][1] + b1);
                Yh[((size_t)b * Ln + r + 8) * YSH + ou] = packh(acc[i][j][2] + b0, acc[i][j][3] + b1);
            }
        }
    } else {
        #pragma unroll
        for (int j = 0; j < 12; j++) {
            int o = o0 + wn + j * 8 + tig * 2;
            if (o >= Oreal) continue;
            float b0 = bias[o], b1 = bias[o + 1];
            #pragma unroll
            for (int i = 0; i < 2; i++) {
                int r = l0 + wm + i * 16 + gid;
                size_t y0 = ((size_t)b * Ln + r) * YS + o;
                size_t y1 = ((size_t)b * Ln + r + 8) * YS + o;
                float2 v0 = make_float2(acc[i][j][0] + b0, acc[i][j][1] + b1);
                float2 v1 = make_float2(acc[i][j][2] + b0, acc[i][j][3] + b1);
                if (resid) {
                    float2 q0 = *(const float2*)(resid + y0);
                    float2 q1 = *(const float2*)(resid + y1);
                    v0.x += q0.x; v0.y += q0.y; v1.x += q1.x; v1.y += q1.y;
                }
                *(float2*)(Yf + y0) = v0;
                *(float2*)(Yf + y1) = v1;
            }
        }
    }
}

// ---------------- transpose in: x[C,L] -> xt[L,C] ----------------
__global__ void t_in(const float* __restrict__ x, float* __restrict__ xt) {
    __shared__ float t[32][33];
    int b = blockIdx.z, l0 = blockIdx.x * 32, c0 = blockIdx.y * 32;
    int tx = threadIdx.x, ty = threadIdx.y;
    #pragma unroll
    for (int k = 0; k < 4; k++)
        t[ty + 8 * k][tx] = x[((size_t)b * Cn + c0 + ty + 8 * k) * Ln + l0 + tx];
    __syncthreads();
    #pragma unroll
    for (int k = 0; k < 4; k++)
        xt[((size_t)b * Ln + l0 + ty + 8 * k) * Cn + c0 + tx] = t[tx][ty + 8 * k];
}

// ---------------- transpose out + residual ----------------
__global__ void t_out(const float* __restrict__ a, const float* __restrict__ y,
                      float* __restrict__ out) {
    __shared__ float t[32][33];
    int b = blockIdx.z, l0 = blockIdx.x * 32, c0 = blockIdx.y * 32;
    int tx = threadIdx.x, ty = threadIdx.y;
    #pragma unroll
    for (int k = 0; k < 4; k++) {
        size_t idx = ((size_t)b * Ln + l0 + ty + 8 * k) * Cn + c0 + tx;
        t[ty + 8 * k][tx] = a[idx] + y[idx];
    }
    __syncthreads();
    #pragma unroll
    for (int k = 0; k < 4; k++)
        out[((size_t)b * Cn + c0 + ty + 8 * k) * Ln + l0 + tx] = t[tx][ty + 8 * k];
}

// ---------------- time MLP: warp-per-output ----------------
__global__ void time_mlp_kernel(const float* __restrict__ t_emb,
                                const float* __restrict__ aw, const float* __restrict__ ab,
                                const float* __restrict__ fw, const float* __restrict__ fb) {
    int bb = blockIdx.x;               // 0..7 : (branch, b)
    int branch = bb >> 2, b = bb & 3;
    const float* w   = branch ? fw : aw;
    const float* bia = branch ? fb : ab;
    __shared__ float ts[TIMED];
    int tid = threadIdx.x, warp = tid >> 5, lane = tid & 31;
    if (tid < TIMED) {
        float t = t_emb[b * TIMED + tid];
        ts[tid] = t / (1.f + expf(-t));
    }
    __syncthreads();
    int o = blockIdx.y * 8 + warp;     // grid.y = 48 -> 384 outputs
    const float* wr = w + (size_t)o * TIMED;
    float s = 0.f;
    #pragma unroll
    for (int i = 0; i < 8; i++) s += ts[lane + 32 * i] * wr[lane + 32 * i];
    #pragma unroll
    for (int off = 16; off; off >>= 1) s += __shfl_xor_sync(0xffffffffu, s, off);
    if (lane == 0)
        g_mod[((size_t)branch * Bn + b) * (2 * Cn) + o] = s + bia[o];
}

// ---------------- LN + modulation -> fp16 pair plane ----------------
__global__ void ln_mod_cl(const float* __restrict__ x, const float* __restrict__ w,
                          const float* __restrict__ bb, int branch,
                          uint32_t* __restrict__ uh) {
    int warp = threadIdx.x >> 5, lane = threadIdx.x & 31;
    int b = blockIdx.y;
    size_t l = (size_t)blockIdx.x * 8 + warp;
    const float* xr = x + ((size_t)b * Ln + l) * Cn;
    float2 v[3];
    float s = 0.f, q = 0.f;
    #pragma unroll
    for (int j = 0; j < 3; j++) {
        v[j] = *(const float2*)(xr + 2 * lane + 64 * j);
        s += v[j].x + v[j].y;
        q += v[j].x * v[j].x + v[j].y * v[j].y;
    }
    #pragma unroll
    for (int off = 16; off; off >>= 1) {
        s += __shfl_xor_sync(0xffffffffu, s, off);
        q += __shfl_xor_sync(0xffffffffu, q, off);
    }
    float mean = s * (1.f / Cn);
    float var  = fmaxf((q - s * mean) * (1.f / (Cn - 1)), 0.f);
    float inv  = 1.f / (sqrtf(var) + 1e-6f);
    const float* md = g_mod + ((size_t)branch * Bn + b) * (2 * Cn);
    size_t ub = ((size_t)b * Ln + l) * 96;
    #pragma unroll
    for (int j = 0; j < 3; j++) {
        int c = 2 * lane + 64 * j;
        float t0 = ((v[j].x - mean) * inv * w[c]     + bb[c])     * (1.f + md[c])     + md[Cn + c];
        float t1 = ((v[j].y - mean) * inv * w[c + 1] + bb[c + 1]) * (1.f + md[c + 1]) + md[Cn + c + 1];
        uh[ub + lane + 32 * j] = packh(t0, t1);
    }
}

// ---------------- qkv depthwise 3x3: fp16 in -> fp16 out, 4 pixels/thread ----------
// Also fuses q/k sum-of-squares (channels 0..383) via atomicAdd.
__global__ void dwconv_cl(const uint32_t* __restrict__ in, const float* __restrict__ w,
                          const float* __restrict__ bias, uint32_t* __restrict__ outp) {
    int c2 = threadIdx.x;
    if (c2 >= 144) return;                 // handles uints 2c2, 2c2+1 (4 channels)
    int g = blockIdx.x, b = blockIdx.z;
    int h = g >> 5, wg = (g & 31) << 2;
    const uint32_t* base = in + (size_t)b * Ln * 288 + 2 * c2;
    float wr[9][4];
    #pragma unroll
    for (int i = 0; i < 4; i++)
        #pragma unroll
        for (int t = 0; t < 9; t++)
            wr[t][i] = __ldg(&w[(c2 * 4 + i) * 9 + t]);
    uint32_t u0[3][6], u1[3][6];
    #pragma unroll
    for (int r = 0; r < 3; r++) {
        int h2 = h + r - 1;
        bool hok = (h2 >= 0 && h2 < Hn);
        #pragma unroll
        for (int p = 0; p < 6; p++) {
            int w2 = wg + p - 1;
            if (hok && w2 >= 0 && w2 < Wn) {
                uint2 uu = *(const uint2*)(base + (size_t)(h2 * Wn + w2) * 288);
                u0[r][p] = uu.x; u1[r][p] = uu.y;
            } else { u0[r][p] = 0u; u1[r][p] = 0u; }
        }
    }
    float b0 = bias[c2 * 4], b1 = bias[c2 * 4 + 1], b2 = bias[c2 * 4 + 2], b3 = bias[c2 * 4 + 3];
    float ss0 = 0.f, ss1 = 0.f, ss2 = 0.f, ss3 = 0.f;
    #pragma unroll
    for (int p = 0; p < 4; p++) {
        float a0 = b0, a1 = b1, a2 = b2, a3 = b3;
        #pragma unroll
        for (int kh = 0; kh < 3; kh++)
            #pragma unroll
            for (int kw = 0; kw < 3; kw++) {
                int t = kh * 3 + kw;
                float2 f0 = unph(u0[kh][p + kw]);
                float2 f1 = unph(u1[kh][p + kw]);
                a0 += wr[t][0] * f0.x; a1 += wr[t][1] * f0.y;
                a2 += wr[t][2] * f1.x; a3 += wr[t][3] * f1.y;
            }
        size_t ob = ((size_t)b * Ln + h * Wn + wg + p) * 288 + 2 * c2;
        outp[ob]     = packh(a0, a1);
        outp[ob + 1] = packh(a2, a3);
        ss0 += a0 * a0; ss1 += a1 * a1; ss2 += a2 * a2; ss3 += a3 * a3;
    }
    if (c2 < 96) {
        float* rn = g_rn + b * (2 * Cn) + 4 * c2;
        atomicAdd(rn,     ss0);
        atomicAdd(rn + 1, ss1);
        atomicAdd(rn + 2, ss2);
        atomicAdd(rn + 3, ss3);
    }
}

// ---------------- GDFN dwconv + gate: fp16 in -> fp16 out, 4 pixels/thread --------
__global__ void dwgate_cl(const uint32_t* __restrict__ in, const float* __restrict__ w,
                          const float* __restrict__ bias, uint32_t* __restrict__ uh) {
    int j = blockIdx.y * 128 + threadIdx.x;   // 0..255
    int g = blockIdx.x, b = blockIdx.z;
    int h = g >> 5, wg = (g & 31) << 2;
    size_t rowb = (size_t)b * Ln;
    if (j == 255) {
        #pragma unroll
        for (int p = 0; p < 4; p++)
            uh[(rowb + h * Wn + wg + p) * 256 + 255] = 0u;
        return;
    }
    int c0 = 2 * j;
    float w1[9][2], w2[9][2];
    #pragma unroll
    for (int i = 0; i < 2; i++)
        #pragma unroll
        for (int t = 0; t < 9; t++) {
            w1[t][i] = __ldg(&w[(c0 + i) * 9 + t]);
            w2[t][i] = __ldg(&w[(510 + c0 + i) * 9 + t]);
        }
    const uint32_t* base = in + rowb * 510;
    uint32_t ua[3][6], ub2[3][6];
    #pragma unroll
    for (int r = 0; r < 3; r++) {
        int h2 = h + r - 1;
        bool hok = (h2 >= 0 && h2 < Hn);
        #pragma unroll
        for (int p = 0; p < 6; p++) {
            int w2i = wg + p - 1;
            if (hok && w2i >= 0 && w2i < Wn) {
                const uint32_t* prow = base + (size_t)(h2 * Wn + w2i) * 510;
                ua[r][p]  = prow[j];
                ub2[r][p] = prow[255 + j];
            } else { ua[r][p] = 0u; ub2[r][p] = 0u; }
        }
    }
    float b10 = bias[c0], b11 = bias[c0 + 1];
    float b20 = bias[510 + c0], b21 = bias[510 + c0 + 1];
    #pragma unroll
    for (int p = 0; p < 4; p++) {
        float a1x = 0.f, a1y = 0.f, a2x = 0.f, a2y = 0.f;
        #pragma unroll
        for (int kh = 0; kh < 3; kh++)
            #pragma unroll
            for (int kw = 0; kw < 3; kw++) {
                int t = kh * 3 + kw;
                float2 f1 = unph(ua[kh][p + kw]);
                float2 f2 = unph(ub2[kh][p + kw]);
                a1x += w1[t][0] * f1.x; a1y += w1[t][1] * f1.y;
                a2x += w2[t][0] * f2.x; a2y += w2[t][1] * f2.y;
            }
        float o0 = (a1x + b10) * (a2x + b20);
        float o1 = (a1y + b11) * (a2y + b21);
        uh[(rowb + h * Wn + wg + p) * 256 + j] = packh(o0, o1);
    }
}

// ---------------- attention logits (fp16 input) ----------------
__global__ void attn_logits_cl(const uint32_t* __restrict__ qk) {
    int bh = blockIdx.y;  int b = bh >> 3, h = bh & 7;
    int l0 = blockIdx.x * 128;
    __shared__ float qs[CH * 129], ks[CH * 129];
    const uint32_t* qbase = qk + ((size_t)b * Ln + l0) * 288 + h * 12;
    const uint32_t* kbase = qbase + 96;
    for (int i = threadIdx.x; i < 12 * 128; i += 256) {
        int l = i / 12, u = i - l * 12;
        float2 fq = unph(qbase[(size_t)l * 288 + u]);
        float2 fk = unph(kbase[(size_t)l * 288 + u]);
        qs[(2 * u) * 129 + l]     = fq.x;
        qs[(2 * u + 1) * 129 + l] = fq.y;
        ks[(2 * u) * 129 + l]     = fk.x;
        ks[(2 * u + 1) * 129 + l] = fk.y;
    }
    __syncthreads();
    int t = threadIdx.x;
    if (t < 144) {
        int c0 = (t / 12) * 2, d0 = (t % 12) * 2;
        float a00 = 0, a01 = 0, a10 = 0, a11 = 0;
        #pragma unroll 4
        for (int l = 0; l < 128; l++) {
            float q0 = qs[c0 * 129 + l], q1 = qs[(c0 + 1) * 129 + l];
            float k0 = ks[d0 * 129 + l], k1 = ks[(d0 + 1) * 129 + l];
            a00 += q0 * k0; a01 += q0 * k1; a10 += q1 * k0; a11 += q1 * k1;
        }
        float* S = g_S + (size_t)bh * (CH * CH);
        atomicAdd(&S[ c0      * CH + d0    ], a00);
        atomicAdd(&S[ c0      * CH + d0 + 1], a01);
        atomicAdd(&S[(c0 + 1) * CH + d0    ], a10);
        atomicAdd(&S[(c0 + 1) * CH + d0 + 1], a11);
    }
}

// ---------------- softmax ----------------
__global__ void attn_softmax_kernel(const float* __restrict__ temp) {
    int bh = blockIdx.x;  int b = bh >> 3, h = bh & 7;
    int c = threadIdx.x;
    if (c >= CH) return;
    float* S = g_S + (size_t)bh * (CH * CH) + c * CH;
    float rq = 1.f / fmaxf(sqrtf(g_rn[b * (2 * Cn) + h * CH + c]), 1e-12f);
    float tp = temp[h];
    float lo[CH];
    float mx = -1e30f;
    #pragma unroll
    for (int d = 0; d < CH; d++) {
        float rk = 1.f / fmaxf(sqrtf(g_rn[b * (2 * Cn) + Cn + h * CH + d]), 1e-12f);
        float v = S[d] * rq * rk * tp;
        lo[d] = v; mx = fmaxf(mx, v);
    }
    float sum = 0.f;
    #pragma unroll
    for (int d = 0; d < CH; d++) { lo[d] = expf(lo[d] - mx); sum += lo[d]; }
    float inv = 1.f / sum;
    #pragma unroll
    for (int d = 0; d < CH; d++) S[d] = lo[d] * inv;
}

// ---------------- attention apply (fp16 v) -> fp16 pair plane ----------------
__global__ void attn_apply_cl(const uint32_t* __restrict__ qkv, uint32_t* __restrict__ uh) {
    int b = blockIdx.z, h = blockIdx.y;
    int l = blockIdx.x * 128 + threadIdx.x;
    __shared__ float P[CH * CH];
    for (int i = threadIdx.x; i < CH * CH; i += 128)
        P[i] = g_S[(size_t)(b * HEADS + h) * (CH * CH) + i];
    __syncthreads();
    const uint32_t* vr = qkv + ((size_t)b * Ln + l) * 288 + 192 + h * 12;
    float vv[CH];
    #pragma unroll
    for (int d = 0; d < 12; d++) {
        float2 f = unph(vr[d]);
        vv[2 * d] = f.x; vv[2 * d + 1] = f.y;
    }
    float acc[CH];
    #pragma unroll
    for (int c = 0; c < CH; c++) {
        float a = 0.f;
        #pragma unroll
        for (int d = 0; d < CH; d++) a += P[c * CH + d] * vv[d];
        acc[c] = a;
    }
    size_t ub = ((size_t)b * Ln + l) * 96 + h * 12;
    #pragma unroll
    for (int i = 0; i < 12; i++)
        uh[ub + i] = packh(acc[2 * i], acc[2 * i + 1]);
}

// ---------------- launch ----------------
extern "C" void kernel_launch(void* const* d_in, const int* in_sizes, int n_in,
                              void* d_out, int out_size) {
    const float* x       = (const float*)d_in[0];
    const float* t_emb   = (const float*)d_in[1];
    const float* n1_w    = (const float*)d_in[2];
    const float* n1_b    = (const float*)d_in[3];
    const float* temp    = (const float*)d_in[4];
    const float* a_qkv_w = (const float*)d_in[5];
    const float* a_qkv_b = (const float*)d_in[6];
    const float* a_dw_w  = (const float*)d_in[7];
    const float* a_dw_b  = (const float*)d_in[8];
    const float* a_proj_w= (const float*)d_in[9];
    const float* a_proj_b= (const float*)d_in[10];
    const float* a_t_w   = (const float*)d_in[11];
    const float* a_t_b   = (const float*)d_in[12];
    const float* n2_w    = (const float*)d_in[13];
    const float* n2_b    = (const float*)d_in[14];
    const float* f_c1_w  = (const float*)d_in[15];
    const float* f_c1_b  = (const float*)d_in[16];
    const float* f_dw_w  = (const float*)d_in[17];
    const float* f_dw_b  = (const float*)d_in[18];
    const float* f_c2_w  = (const float*)d_in[19];
    const float* f_c2_b  = (const float*)d_in[20];
    const float* f_t_w   = (const float*)d_in[21];
    const float* f_t_b   = (const float*)d_in[22];
    float* out = (float*)d_out;

    float *p_y, *p_x1, *p_xt, *p_S, *p_rn;
    uint32_t *p_wh, *p_ah, *p_bufA, *p_bufB;
    cudaGetSymbolAddress((void**)&p_y,    g_y);
    cudaGetSymbolAddress((void**)&p_x1,   g_x1);
    cudaGetSymbolAddress((void**)&p_xt,   g_xt);
    cudaGetSymbolAddress((void**)&p_bufA, g_bufA);
    cudaGetSymbolAddress((void**)&p_bufB, g_bufB);
    cudaGetSymbolAddress((void**)&p_S,    g_S);
    cudaGetSymbolAddress((void**)&p_rn,   g_rn);
    cudaGetSymbolAddress((void**)&p_wh,   g_wh);
    cudaGetSymbolAddress((void**)&p_ah,   g_ah);

    prep_all<<<dim3(108, 4), 256>>>(a_qkv_w, a_proj_w, f_c1_w, f_c2_w, p_wh);

    cudaMemsetAsync(p_S,  0, sizeof(float) * Bn * HEADS * CH * CH);
    cudaMemsetAsync(p_rn, 0, sizeof(float) * Bn * 2 * Cn);

    time_mlp_kernel<<<dim3(8, 48), 256>>>(t_emb, a_t_w, a_t_b, f_t_w, f_t_b);
    t_in<<<dim3(Ln / 32, Cn / 32, Bn), dim3(32, 8)>>>(x, p_xt);

    // ================= Block 1: MDTA =================
    ln_mod_cl<<<dim3(Ln / 8, Bn), 256>>>(p_xt, n1_w, n1_b, 0, p_ah);
    mma_hmma<<<dim3(Ln / 128, 3, Bn), 256>>>(p_ah, 96, p_wh, 96,
                                             a_qkv_b, nullptr, nullptr, p_bufA, 288, 0, 576, 12);
    dwconv_cl<<<dim3(Ln / 4, 1, Bn), 160>>>(p_bufA, a_dw_w, a_dw_b, p_bufB);
    attn_logits_cl<<<dim3(Ln / 128, Bn * HEADS), 256>>>(p_bufB);
    attn_softmax_kernel<<<Bn * HEADS, 32>>>(temp);
    attn_apply_cl<<<dim3(Ln / 128, HEADS, Bn), 128>>>(p_bufB, p_ah);
    mma_hmma<<<dim3(Ln / 128, 1, Bn), 256>>>(p_ah, 96, p_wh + 55296, 96,
                                             a_proj_b, p_xt, p_x1, nullptr, 0, 192, 192, 12);

    // ================= Block 2: GDFN =================
    ln_mod_cl<<<dim3(Ln / 8, Bn), 256>>>(p_x1, n2_w, n2_b, 1, p_ah);
    mma_hmma<<<dim3(Ln / 128, 6, Bn), 256>>>(p_ah, 96, p_wh + 73728, 96,
                                             f_c1_b, nullptr, nullptr, p_bufA, 510, 0, 1020, 12);
    dwgate_cl<<<dim3(Ln / 4, 2, Bn), 128>>>(p_bufA, f_dw_w, f_dw_b, p_ah);
    mma_hmma<<<dim3(Ln / 128, 1, Bn), 256>>>(p_ah, 256, p_wh + 184320, 256,
                                             f_c2_b, nullptr, p_y, nullptr, 0, 192, 192, 32);
    t_out<<<dim3(Ln / 32, Cn / 32, Bn), dim3(32, 8)>>>(p_x1, p_y, out);
}